// round 2
// baseline (speedup 1.0000x reference)
#include <cuda_runtime.h>
#include <cstdint>

// ---------------- scratch (device globals; no allocation allowed) ----------
__device__ float g_h1[8192 * 5 * 30 * 30];   // conv1 pooled output
__device__ float g_h2[8192 * 1696];          // conv2 feats (1690) + ds(3) + pad(3)
__device__ float g_f1[8192 * 512];
__device__ float g_f2[8192 * 256];
__device__ float g_f3[8192 * 128];
__device__ float g_f4[8192 * 64];

// ---------------- conv1 + relu + maxpool ----------------
// one image per block. out: g_h1[b][c][30][30]
__global__ void __launch_bounds__(256) conv1_kernel(
    const float* __restrict__ x, const float* __restrict__ w1,
    const float* __restrict__ b1)
{
    __shared__ float simg[64 * 64];
    __shared__ float sw[125];
    __shared__ float sb[5];
    int b = blockIdx.x;
    int tid = threadIdx.x;
    const float* xr = x + (size_t)b * 4099 + 3;
    for (int i = tid; i < 4096; i += 256) simg[i] = xr[i];
    if (tid < 125) sw[tid] = w1[tid];
    if (tid < 5)   sb[tid] = b1[tid];
    __syncthreads();

    for (int p = tid; p < 900; p += 256) {
        int py = p / 30, px = p % 30;
        float win[6][6];
        const float* wp = &simg[(2 * py) * 64 + 2 * px];
#pragma unroll
        for (int r = 0; r < 6; r++)
#pragma unroll
            for (int c = 0; c < 6; c++)
                win[r][c] = wp[r * 64 + c];

#pragma unroll
        for (int ch = 0; ch < 5; ch++) {
            float a00 = 0.f, a01 = 0.f, a10 = 0.f, a11 = 0.f;
#pragma unroll
            for (int i = 0; i < 5; i++)
#pragma unroll
                for (int j = 0; j < 5; j++) {
                    float w = sw[ch * 25 + i * 5 + j];
                    a00 = fmaf(win[i][j],     w, a00);
                    a01 = fmaf(win[i][j + 1], w, a01);
                    a10 = fmaf(win[i + 1][j], w, a10);
                    a11 = fmaf(win[i + 1][j + 1], w, a11);
                }
            float m = fmaxf(fmaxf(a00, a01), fmaxf(a10, a11));
            float v = fmaxf(m + sb[ch], 0.f);
            g_h1[(((size_t)b * 5 + ch) * 30 + py) * 30 + px] = v;
        }
    }
}

// ---------------- conv2 + relu + maxpool + ds concat ----------------
// 2 images per block, 352 threads. out: g_h2[b][oc*169 + p], ds at 1690..1692
__global__ void __launch_bounds__(352) conv2_kernel(
    const float* __restrict__ x, const float* __restrict__ w2,
    const float* __restrict__ b2)
{
    __shared__ float sh[2 * 4500];
    __shared__ float sw[1250];
    __shared__ float sb[10];
    int tid = threadIdx.x;
    int ib = blockIdx.x * 2;
    const float* src = &g_h1[(size_t)ib * 4500];
    for (int i = tid; i < 9000; i += 352) sh[i] = src[i];
    for (int i = tid; i < 1250; i += 352) sw[i] = w2[i];
    if (tid < 10) sb[tid] = b2[tid];
    __syncthreads();

    if (tid < 338) {
        int il = tid / 169;
        int p  = tid % 169;
        int b  = ib + il;
        int py = p / 13, px = p % 13;
        float acc[10][4];
#pragma unroll
        for (int o = 0; o < 10; o++)
            acc[o][0] = acc[o][1] = acc[o][2] = acc[o][3] = 0.f;
        const float* base = &sh[il * 4500];
#pragma unroll 1
        for (int ic = 0; ic < 5; ic++) {
            float win[6][6];
            const float* wp = base + ic * 900 + (2 * py) * 30 + 2 * px;
#pragma unroll
            for (int r = 0; r < 6; r++)
#pragma unroll
                for (int c = 0; c < 6; c++)
                    win[r][c] = wp[r * 30 + c];
#pragma unroll
            for (int oc = 0; oc < 10; oc++) {
                const float* wgt = &sw[(oc * 5 + ic) * 25];
#pragma unroll
                for (int i = 0; i < 5; i++)
#pragma unroll
                    for (int j = 0; j < 5; j++) {
                        float w = wgt[i * 5 + j];
                        acc[oc][0] = fmaf(win[i][j],         w, acc[oc][0]);
                        acc[oc][1] = fmaf(win[i][j + 1],     w, acc[oc][1]);
                        acc[oc][2] = fmaf(win[i + 1][j],     w, acc[oc][2]);
                        acc[oc][3] = fmaf(win[i + 1][j + 1], w, acc[oc][3]);
                    }
            }
        }
        float* dst = &g_h2[(size_t)b * 1696];
#pragma unroll
        for (int oc = 0; oc < 10; oc++) {
            float m = fmaxf(fmaxf(acc[oc][0], acc[oc][1]),
                            fmaxf(acc[oc][2], acc[oc][3]));
            dst[oc * 169 + p] = fmaxf(m + sb[oc], 0.f);
        }
    } else if (tid < 338 + 6) {
        int i = tid - 338;
        int il = i / 3, j = i % 3;
        int b = ib + il;
        g_h2[(size_t)b * 1696 + 1690 + j] = x[(size_t)b * 4099 + j];
    }
}

// ---------------- generic tiled SGEMM: C = relu(A @ W^T + bias) -----------
// A: [M,K] row-major (stride lda), W: [N,K] row-major (stride ldw)
template <int BM, int BN, int BK, int TM, int TN, bool RELU>
__global__ void __launch_bounds__(256) gemm_bias_relu(
    const float* __restrict__ A, int lda,
    const float* __restrict__ W, int ldw,
    const float* __restrict__ bias,
    float* __restrict__ C, int ldc, int K)
{
    __shared__ float As[BK][BM + 4];
    __shared__ float Bs[BK][BN + 4];
    int tid = threadIdx.x;
    int m0 = blockIdx.x * BM;
    int n0 = blockIdx.y * BN;
    constexpr int TDM = BM / TM;
    int tidm = tid % TDM;
    int tidn = tid / TDM;

    float acc[TM][TN];
#pragma unroll
    for (int i = 0; i < TM; i++)
#pragma unroll
        for (int j = 0; j < TN; j++) acc[i][j] = 0.f;

    constexpr int A_VEC = (BM * BK) / (256 * 4);  // float4 loads per thread
    constexpr int B_SC  = (BN * BK) / 256;        // scalar loads per thread

    for (int k0 = 0; k0 < K; k0 += BK) {
        // stage A tile (vectorized, K-guarded)
#pragma unroll
        for (int v = 0; v < A_VEC; v++) {
            int idx = tid + v * 256;
            int row = idx / (BK / 4);
            int c4  = idx % (BK / 4);
            int k   = k0 + c4 * 4;
            const float* ap = &A[(size_t)(m0 + row) * lda + k];
            float4 val;
            if (k + 3 < K) {
                val = *(const float4*)ap;
            } else {
                val.x = (k + 0 < K) ? ap[0] : 0.f;
                val.y = (k + 1 < K) ? ap[1] : 0.f;
                val.z = (k + 2 < K) ? ap[2] : 0.f;
                val.w = (k + 3 < K) ? ap[3] : 0.f;
            }
            As[c4 * 4 + 0][row] = val.x;
            As[c4 * 4 + 1][row] = val.y;
            As[c4 * 4 + 2][row] = val.z;
            As[c4 * 4 + 3][row] = val.w;
        }
        // stage W tile (scalar, rows may be unaligned; K-guarded)
#pragma unroll
        for (int v = 0; v < B_SC; v++) {
            int idx = tid + v * 256;
            int n = idx / BK;
            int k = idx % BK;
            float val = (k0 + k < K) ? W[(size_t)(n0 + n) * ldw + k0 + k] : 0.f;
            Bs[k][n] = val;
        }
        __syncthreads();

#pragma unroll
        for (int kk = 0; kk < BK; kk++) {
            float ar[TM], br[TN];
#pragma unroll
            for (int i = 0; i < TM / 4; i++) {
                float4 v = *(const float4*)&As[kk][tidm * TM + i * 4];
                ar[i * 4] = v.x; ar[i * 4 + 1] = v.y;
                ar[i * 4 + 2] = v.z; ar[i * 4 + 3] = v.w;
            }
#pragma unroll
            for (int j = 0; j < TN / 4; j++) {
                float4 v = *(const float4*)&Bs[kk][tidn * TN + j * 4];
                br[j * 4] = v.x; br[j * 4 + 1] = v.y;
                br[j * 4 + 2] = v.z; br[j * 4 + 3] = v.w;
            }
#pragma unroll
            for (int i = 0; i < TM; i++)
#pragma unroll
                for (int j = 0; j < TN; j++)
                    acc[i][j] = fmaf(ar[i], br[j], acc[i][j]);
        }
        __syncthreads();
    }

    float bj[TN];
#pragma unroll
    for (int j = 0; j < TN; j++) bj[j] = bias[n0 + tidn * TN + j];
#pragma unroll
    for (int i = 0; i < TM; i++) {
        int row = m0 + tidm * TM + i;
#pragma unroll
        for (int j4 = 0; j4 < TN / 4; j4++) {
            float4 v;
            float v0 = acc[i][j4 * 4 + 0] + bj[j4 * 4 + 0];
            float v1 = acc[i][j4 * 4 + 1] + bj[j4 * 4 + 1];
            float v2 = acc[i][j4 * 4 + 2] + bj[j4 * 4 + 2];
            float v3 = acc[i][j4 * 4 + 3] + bj[j4 * 4 + 3];
            if (RELU) {
                v0 = fmaxf(v0, 0.f); v1 = fmaxf(v1, 0.f);
                v2 = fmaxf(v2, 0.f); v3 = fmaxf(v3, 0.f);
            }
            v.x = v0; v.y = v1; v.z = v2; v.w = v3;
            *(float4*)&C[(size_t)row * ldc + n0 + tidn * TN + j4 * 4] = v;
        }
    }
}

// ---------------- head: fc5 + softmax + expert blend ----------------
__global__ void __launch_bounds__(128) head_kernel(
    const float* __restrict__ fc5w, const float* __restrict__ fc5b,
    const float* __restrict__ Bm, const float* __restrict__ Cm,
    const float* __restrict__ x, const float* __restrict__ xt,
    float* __restrict__ out)
{
    __shared__ float sw[1024];
    __shared__ float sb[16];
    __shared__ float sA[144];
    __shared__ float st[3];
    int tid = threadIdx.x;
    for (int i = tid; i < 1024; i += 128) sw[i] = fc5w[i];
    if (tid < 16)  sb[tid] = fc5b[tid];
    // BUGFIX (R0): 144 > blockDim(128); must stride, else experts 14/15
    // read uninitialized shared memory (caused rel_err = 0.16).
    for (int i = tid; i < 144; i += 128) sA[i] = Bm[i] + Cm[i];
    if (tid < 3)   st[tid] = xt[tid];
    __syncthreads();

    int s = blockIdx.x * 128 + tid;
    const float* f = &g_f4[(size_t)s * 64];
    float fr[64];
#pragma unroll
    for (int i = 0; i < 16; i++) {
        float4 v = *(const float4*)&f[i * 4];
        fr[i * 4] = v.x; fr[i * 4 + 1] = v.y;
        fr[i * 4 + 2] = v.z; fr[i * 4 + 3] = v.w;
    }
    float logit[16];
    float mx = -1e30f;
#pragma unroll
    for (int n = 0; n < 16; n++) {
        float a = sb[n];
#pragma unroll
        for (int k = 0; k < 64; k++) a = fmaf(fr[k], sw[n * 64 + k], a);
        logit[n] = a;
        mx = fmaxf(mx, a);
    }
    float sum = 0.f;
#pragma unroll
    for (int n = 0; n < 16; n++) { logit[n] = expf(logit[n] - mx); sum += logit[n]; }
    float inv = 1.f / sum;

    float d0 = st[0] - x[(size_t)s * 4099 + 0];
    float d1 = st[1] - x[(size_t)s * 4099 + 1];
    float d2 = st[2] - x[(size_t)s * 4099 + 2];
    float o0 = 0.f, o1 = 0.f, o2 = 0.f;
#pragma unroll
    for (int n = 0; n < 16; n++) {
        float w = logit[n] * inv;
        const float* An = &sA[n * 9];
        o0 += w * (An[0] * d0 + An[1] * d1 + An[2] * d2);
        o1 += w * (An[3] * d0 + An[4] * d1 + An[5] * d2);
        o2 += w * (An[6] * d0 + An[7] * d1 + An[8] * d2);
    }
    out[(size_t)s * 3 + 0] = o0;
    out[(size_t)s * 3 + 1] = o1;
    out[(size_t)s * 3 + 2] = o2;
}

// ---------------- launch ----------------
extern "C" void kernel_launch(void* const* d_in, const int* in_sizes, int n_in,
                              void* d_out, int out_size)
{
    const float* x    = (const float*)d_in[0];
    const float* w1   = (const float*)d_in[1];
    const float* b1   = (const float*)d_in[2];
    const float* w2   = (const float*)d_in[3];
    const float* b2   = (const float*)d_in[4];
    const float* fc1w = (const float*)d_in[5];
    const float* fc1b = (const float*)d_in[6];
    const float* fc2w = (const float*)d_in[7];
    const float* fc2b = (const float*)d_in[8];
    const float* fc3w = (const float*)d_in[9];
    const float* fc3b = (const float*)d_in[10];
    const float* fc4w = (const float*)d_in[11];
    const float* fc4b = (const float*)d_in[12];
    const float* fc5w = (const float*)d_in[13];
    const float* fc5b = (const float*)d_in[14];
    const float* Bm   = (const float*)d_in[15];
    const float* Cm   = (const float*)d_in[16];
    const float* xt   = (const float*)d_in[17];

    int B = in_sizes[0] / 4099;  // 8192

    float *h2, *f1, *f2, *f3, *f4;
    cudaGetSymbolAddress((void**)&h2, g_h2);
    cudaGetSymbolAddress((void**)&f1, g_f1);
    cudaGetSymbolAddress((void**)&f2, g_f2);
    cudaGetSymbolAddress((void**)&f3, g_f3);
    cudaGetSymbolAddress((void**)&f4, g_f4);

    conv1_kernel<<<B, 256>>>(x, w1, b1);
    conv2_kernel<<<B / 2, 352>>>(x, w2, b2);

    gemm_bias_relu<128, 128, 16, 8, 8, true>
        <<<dim3(B / 128, 512 / 128), 256>>>(h2, 1696, fc1w, 1693, fc1b, f1, 512, 1693);
    gemm_bias_relu<128, 128, 16, 8, 8, true>
        <<<dim3(B / 128, 256 / 128), 256>>>(f1, 512, fc2w, 512, fc2b, f2, 256, 512);
    gemm_bias_relu<64, 64, 16, 4, 4, true>
        <<<dim3(B / 64, 128 / 64), 256>>>(f2, 256, fc3w, 256, fc3b, f3, 128, 256);
    gemm_bias_relu<64, 64, 16, 4, 4, true>
        <<<dim3(B / 64, 64 / 64), 256>>>(f3, 128, fc4w, 128, fc4b, f4, 64, 128);

    head_kernel<<<B / 128, 128>>>(fc5w, fc5b, Bm, Cm, x, xt, (float*)d_out);
}